// round 8
// baseline (speedup 1.0000x reference)
#include <cuda_runtime.h>
#include <cstdint>

// Problem constants
#define BATCH 64
#define HDIM 56
#define WDIM 56
#define CDIM 256
#define ROUTES 4
#define CONV_OUT 64
#define ROUTE_W 64            // C / ROUTES
#define ROWG 14               // groups per image: 4 rows each
#define NSTAT 9
#define BN_EPS 1e-3f

// Scratch (device globals — no allocation allowed)
__device__ float4 g_acc[BATCH * ROWG];    // per-(batch,group) logit contribution, 14 KB
__device__ float  g_W[9 * CDIM * ROUTES]; // folded conv@fc weights / 784
__device__ int    g_route[BATCH];

// float4 helpers (component-wise over the 4 routes)
__device__ __forceinline__ float4 f4add(float4 a, float4 b) {
    return make_float4(a.x + b.x, a.y + b.y, a.z + b.z, a.w + b.w);
}
__device__ __forceinline__ float4 f4fma(float s, float4 a, float4 acc) {
    return make_float4(fmaf(s, a.x, acc.x), fmaf(s, a.y, acc.y),
                       fmaf(s, a.z, acc.z), fmaf(s, a.w, acc.w));
}
__device__ __forceinline__ float4 f4scale(float s, float4 a) {
    return make_float4(s * a.x, s * a.y, s * a.z, s * a.w);
}

// ---------------------------------------------------------------------------
// Kernel 0: fold conv_w [3,3,256,64] with fc_w [64,4]:
//   g_W[k][ci][r] = (1/784) * sum_co conv_w[k][ci][co] * fc_w[co][r]
// ---------------------------------------------------------------------------
__global__ __launch_bounds__(CDIM) void k_weff(const float* __restrict__ conv_w,
                                               const float* __restrict__ fc_w)
{
    __shared__ float sf[CONV_OUT * ROUTES];
    const int k  = blockIdx.x;
    const int ci = threadIdx.x;
    sf[ci] = fc_w[ci];
    __syncthreads();

    const float* cw = conv_w + ((size_t)k * CDIM + ci) * CONV_OUT;
    float a0 = 0.f, a1 = 0.f, a2 = 0.f, a3 = 0.f;
    #pragma unroll 16
    for (int co = 0; co < CONV_OUT; ++co) {
        float wv = cw[co];
        a0 += wv * sf[co * 4 + 0];
        a1 += wv * sf[co * 4 + 1];
        a2 += wv * sf[co * 4 + 2];
        a3 += wv * sf[co * 4 + 3];
    }
    const float inv = 1.0f / 784.0f;
    float* o = g_W + ((size_t)k * CDIM + ci) * ROUTES;
    o[0] = a0 * inv; o[1] = a1 * inv; o[2] = a2 * inv; o[3] = a3 * inv;
}

// ---------------------------------------------------------------------------
// Kernel 1: sufficient statistics, contracted in-block to a 4-float logit
// contribution per (batch, rowgroup).
//
// 256 threads = 4 row-slices (s = tid>>6) x 64 channel-quads (c4 = tid&63).
// Slice s covers row h = g*4 + s (fixed parity), 56 float4 loads in batches
// of 8 (MLP=8). Reducer (tid<64) combines parities, then contracts the
// 9 stats x 4 channels against scale*W into a float4 over routes, which is
// block-reduced and stored to g_acc (16 bytes per block).
// stats j: 0=EE 1=EO 2=OE 3=OO 4=R0E 5=R0O 6=C0E 7=C0O 8=P00
// ---------------------------------------------------------------------------
__global__ __launch_bounds__(256, 4) void k_stats(const float* __restrict__ in,
                                                  const float* __restrict__ gamma,
                                                  const float* __restrict__ mvar)
{
    const int tid = threadIdx.x;
    const int b  = blockIdx.y;
    const int g  = blockIdx.x;            // 0..13
    const int c4 = tid & 63;
    const int s  = tid >> 6;              // row within group, 0..3

    const int h = g * 4 + s;
    const float4* row = (const float4*)(in
        + (((size_t)b * HDIM + h) * WDIM) * CDIM) + c4;

    float4 Z = {0.f, 0.f, 0.f, 0.f};
    float4 sE = Z, sO = Z, c0 = Z;

    #pragma unroll
    for (int i = 0; i < 7; ++i) {
        // 8 independent loads issued before any accumulation (MLP = 8)
        float4 v0 = row[(size_t)(8 * i + 0) * (CDIM/4)];
        float4 v1 = row[(size_t)(8 * i + 1) * (CDIM/4)];
        float4 v2 = row[(size_t)(8 * i + 2) * (CDIM/4)];
        float4 v3 = row[(size_t)(8 * i + 3) * (CDIM/4)];
        float4 v4 = row[(size_t)(8 * i + 4) * (CDIM/4)];
        float4 v5 = row[(size_t)(8 * i + 5) * (CDIM/4)];
        float4 v6 = row[(size_t)(8 * i + 6) * (CDIM/4)];
        float4 v7 = row[(size_t)(8 * i + 7) * (CDIM/4)];
        if (i == 0) c0 = v0;
        sE.x += (v0.x + v2.x) + (v4.x + v6.x);
        sE.y += (v0.y + v2.y) + (v4.y + v6.y);
        sE.z += (v0.z + v2.z) + (v4.z + v6.z);
        sE.w += (v0.w + v2.w) + (v4.w + v6.w);
        sO.x += (v1.x + v3.x) + (v5.x + v7.x);
        sO.y += (v1.y + v3.y) + (v5.y + v7.y);
        sO.z += (v1.z + v3.z) + (v5.z + v7.z);
        sO.w += (v1.w + v3.w) + (v5.w + v7.w);
    }

    __shared__ float4 sm[4][3][64];       // 12 KB
    sm[s][0][c4] = sE;
    sm[s][1][c4] = sO;
    sm[s][2][c4] = c0;
    __syncthreads();

    __shared__ float4 sred[2];
    float4 acc4 = Z;
    if (tid < 64) {
        float4 e0 = sm[0][0][tid], o0 = sm[0][1][tid], z0 = sm[0][2][tid]; // row g*4+0 (even)
        float4 e1 = sm[1][0][tid], o1 = sm[1][1][tid], z1 = sm[1][2][tid]; // row g*4+1 (odd)
        float4 e2 = sm[2][0][tid], o2 = sm[2][1][tid], z2 = sm[2][2][tid]; // row g*4+2 (even)
        float4 e3 = sm[3][0][tid], o3 = sm[3][1][tid], z3 = sm[3][2][tid]; // row g*4+3 (odd)

        float4 st[NSTAT];
        st[0] = f4add(e0, e2);            // EE
        st[1] = f4add(o0, o2);            // EO
        st[2] = f4add(e1, e3);            // OE
        st[3] = f4add(o1, o3);            // OO
        st[6] = f4add(z0, z2);            // C0E
        st[7] = f4add(z1, z3);            // C0O
        if (g == 0) { st[4] = e0; st[5] = o0; st[8] = z0; }
        else        { st[4] = Z;  st[5] = Z;  st[8] = Z;  }

        // BN scale for channels 4*tid..4*tid+3
        float4 gam = ((const float4*)gamma)[tid];
        float4 mv  = ((const float4*)mvar)[tid];
        float sc[4];
        sc[0] = rsqrtf(mv.x + BN_EPS) * gam.x;
        sc[1] = rsqrtf(mv.y + BN_EPS) * gam.y;
        sc[2] = rsqrtf(mv.z + BN_EPS) * gam.z;
        sc[3] = rsqrtf(mv.w + BN_EPS) * gam.w;

        const float4* W4 = (const float4*)g_W;   // [k][ci] -> float4 over routes
        #pragma unroll
        for (int cc = 0; cc < 4; ++cc) {
            const int ci = 4 * tid + cc;
            float4 W0 = W4[0 * CDIM + ci], W1 = W4[1 * CDIM + ci], W2 = W4[2 * CDIM + ci];
            float4 W3 = W4[3 * CDIM + ci], W4v = W4[4 * CDIM + ci], W5 = W4[5 * CDIM + ci];
            float4 W6 = W4[6 * CDIM + ci], W7 = W4[7 * CDIM + ci], W8 = W4[8 * CDIM + ci];

            float4 tEE  = f4add(f4add(W0, W2), f4add(W6, W8));
            float4 tEO  = f4add(W1, W7);
            float4 tOE  = f4add(W3, W5);
            float4 tR0E = f4add(W6, W8);
            float4 tC0E = f4add(W2, W8);

            float4 d = Z;
            d = f4fma( ((const float*)&st[0])[cc], tEE,  d);
            d = f4fma( ((const float*)&st[1])[cc], tEO,  d);
            d = f4fma( ((const float*)&st[2])[cc], tOE,  d);
            d = f4fma( ((const float*)&st[3])[cc], W4v,  d);
            d = f4fma(-((const float*)&st[4])[cc], tR0E, d);
            d = f4fma(-((const float*)&st[5])[cc], W7,   d);
            d = f4fma(-((const float*)&st[6])[cc], tC0E, d);
            d = f4fma(-((const float*)&st[7])[cc], W5,   d);
            d = f4fma( ((const float*)&st[8])[cc], W8,   d);
            acc4 = f4fma(sc[cc], d, acc4);
        }

        // warp reduce (2 full warps among tid<64)
        #pragma unroll
        for (int o = 16; o > 0; o >>= 1) {
            acc4.x += __shfl_xor_sync(0xFFFFFFFFu, acc4.x, o);
            acc4.y += __shfl_xor_sync(0xFFFFFFFFu, acc4.y, o);
            acc4.z += __shfl_xor_sync(0xFFFFFFFFu, acc4.z, o);
            acc4.w += __shfl_xor_sync(0xFFFFFFFFu, acc4.w, o);
        }
        if ((tid & 31) == 0) sred[tid >> 5] = acc4;
    }
    __syncthreads();
    if (tid == 0)
        g_acc[b * ROWG + g] = f4add(sred[0], sred[1]);
}

// ---------------------------------------------------------------------------
// Kernel 2: finalize routing. grid <<<4, 256>>>, each block: 16 batches.
// Bias term (batch-independent) computed redundantly per block:
//   bias[r] = sum_ci offs_ci*nsum_r(ci) + sum_co conv_b*fc_w + fc_b
// Then per batch: sum 14 group contributions + bias, argmax.
// ---------------------------------------------------------------------------
__global__ __launch_bounds__(CDIM) void k_routefinal(const float* __restrict__ gamma,
                                                     const float* __restrict__ beta,
                                                     const float* __restrict__ mmean,
                                                     const float* __restrict__ mvar,
                                                     const float* __restrict__ conv_b,
                                                     const float* __restrict__ fc_w,
                                                     const float* __restrict__ fc_b,
                                                     float* __restrict__ out_routing)
{
    const int ci   = threadIdx.x;
    const int wid  = ci >> 5;
    const int lane = ci & 31;
    float4 Z = {0.f, 0.f, 0.f, 0.f};

    // ---- bias partial for this channel ----
    const float4* W4 = (const float4*)g_W;
    float4 W0 = W4[0 * CDIM + ci], W1 = W4[1 * CDIM + ci], W2 = W4[2 * CDIM + ci];
    float4 W3 = W4[3 * CDIM + ci], W4v = W4[4 * CDIM + ci], W5 = W4[5 * CDIM + ci];
    float4 W6 = W4[6 * CDIM + ci], W7 = W4[7 * CDIM + ci], W8 = W4[8 * CDIM + ci];

    float4 s784 = f4add(f4add(W0, W1), f4add(W3, W4v));
    float4 s756 = f4add(f4add(W2, W5), f4add(W6, W7));
    float4 nsum = f4fma(784.f, s784, f4fma(756.f, s756, f4scale(729.f, W8)));

    float sc = rsqrtf(mvar[ci] + BN_EPS) * gamma[ci];
    float of = beta[ci] - mmean[ci] * sc;
    float4 part = f4scale(of, nsum);
    if (ci < CONV_OUT)
        part = f4fma(conv_b[ci], ((const float4*)fc_w)[ci], part);

    #pragma unroll
    for (int o = 16; o > 0; o >>= 1) {
        part.x += __shfl_xor_sync(0xFFFFFFFFu, part.x, o);
        part.y += __shfl_xor_sync(0xFFFFFFFFu, part.y, o);
        part.z += __shfl_xor_sync(0xFFFFFFFFu, part.z, o);
        part.w += __shfl_xor_sync(0xFFFFFFFFu, part.w, o);
    }
    __shared__ float4 bred[8];
    if (lane == 0) bred[wid] = part;
    __syncthreads();
    __shared__ float4 bias_s;
    if (ci == 0) {
        float4 bsum = Z;
        #pragma unroll
        for (int w = 0; w < 8; ++w) bsum = f4add(bsum, bred[w]);
        bsum.x += fc_b[0]; bsum.y += fc_b[1]; bsum.z += fc_b[2]; bsum.w += fc_b[3];
        bias_s = bsum;
    }
    __syncthreads();
    const float4 bias = bias_s;

    // ---- per-batch finalization: warp wid handles 2 batches ----
    #pragma unroll
    for (int it = 0; it < 2; ++it) {
        const int b = blockIdx.x * 16 + wid * 2 + it;
        float4 v = (lane < ROWG) ? g_acc[b * ROWG + lane] : Z;
        #pragma unroll
        for (int o = 16; o > 0; o >>= 1) {
            v.x += __shfl_xor_sync(0xFFFFFFFFu, v.x, o);
            v.y += __shfl_xor_sync(0xFFFFFFFFu, v.y, o);
            v.z += __shfl_xor_sync(0xFFFFFFFFu, v.z, o);
            v.w += __shfl_xor_sync(0xFFFFFFFFu, v.w, o);
        }
        if (lane == 0) {
            v = f4add(v, bias);
            int best = 0; float bv = v.x;
            if (v.y > bv) { bv = v.y; best = 1; }
            if (v.z > bv) { bv = v.z; best = 2; }
            if (v.w > bv) { bv = v.w; best = 3; }
            g_route[b] = best;
            ((float4*)out_routing)[b] = v;
        }
    }
}

// ---------------------------------------------------------------------------
// Kernel 3: gather selected 64-channel slab. 4 float4 per thread, reverse
// scheduled so the input tail (L2-resident after k_stats) is gathered first.
// ---------------------------------------------------------------------------
#define G_F4_PER_B (HDIM * WDIM * ROUTE_W / 4)   // 12544
__global__ __launch_bounds__(256) void k_gather(const float* __restrict__ in,
                                                float* __restrict__ out)
{
    const int b = (BATCH - 1) - blockIdx.y;
    const int route = g_route[b];
    const int bx = (gridDim.x - 1) - blockIdx.x;
    const int base = bx * 1024 + threadIdx.x;

    const float4* src4 = (const float4*)in + (size_t)b * (HDIM * WDIM) * (CDIM / 4)
                       + route * (ROUTE_W / 4);
    float4* dst4 = (float4*)out + (size_t)b * G_F4_PER_B;

    #pragma unroll
    for (int m = 0; m < 4; ++m) {
        const int t = base + m * 256;
        if (t < G_F4_PER_B) {
            const int pixel = t >> 4;
            const int q = t & 15;
            dst4[t] = src4[(size_t)pixel * (CDIM / 4) + q];
        }
    }
}

// ---------------------------------------------------------------------------
extern "C" void kernel_launch(void* const* d_in, const int* in_sizes, int n_in,
                              void* d_out, int out_size)
{
    const float* inputs  = (const float*)d_in[0];
    const float* gamma   = (const float*)d_in[1];
    const float* beta    = (const float*)d_in[2];
    const float* mmean   = (const float*)d_in[3];
    const float* mvar    = (const float*)d_in[4];
    const float* conv_w  = (const float*)d_in[5];
    const float* conv_b  = (const float*)d_in[6];
    const float* fc_w    = (const float*)d_in[7];
    const float* fc_b    = (const float*)d_in[8];

    float* out = (float*)d_out;
    // output layout: x [64,56,56,64] then routing_x [64,4]
    float* out_routing = out + ((size_t)out_size - BATCH * ROUTES);

    k_weff<<<9, CDIM>>>(conv_w, fc_w);
    k_stats<<<dim3(ROWG, BATCH), 256>>>(inputs, gamma, mvar);
    k_routefinal<<<4, CDIM>>>(gamma, beta, mmean, mvar, conv_b, fc_w, fc_b, out_routing);
    k_gather<<<dim3((G_F4_PER_B + 1023) / 1024, BATCH), 256>>>(inputs, out);
}

// round 10
// speedup vs baseline: 1.0922x; 1.0922x over previous
#include <cuda_runtime.h>
#include <cstdint>

// NOTE: resubmission of the R8 kernel — the R9 bench failed with
// "system not yet initialized" (container/driver init), before our code ran.

// Problem constants
#define BATCH 64
#define HDIM 56
#define WDIM 56
#define CDIM 256
#define ROUTES 4
#define CONV_OUT 64
#define ROUTE_W 64            // C / ROUTES
#define ROWG 14               // groups per image: 4 rows each
#define NSTAT 9
#define BN_EPS 1e-3f

// Scratch (device globals — no allocation allowed)
__device__ float g_part[BATCH * ROWG * NSTAT * CDIM];   // 8.3 MB, fully overwritten each call
__device__ float g_W[9 * CDIM * ROUTES];                // folded conv@fc weights / 784
__device__ int   g_route[BATCH];

// ---------------------------------------------------------------------------
// Kernel 1: sufficient statistics (+ fused weight-fold slice).
// grid (14, 65): y<64 -> stats for (batch=y, rowgroup=x); y==64, x<9 -> weff.
//
// Stats blocks: 256 threads = 4 row-slices (s = tid>>6) x 64 channel-quads
// (c4 = tid&63). Slice s covers the whole row h = g*4 + s (fixed parity),
// 56 float4 loads per thread issued in 4 batches of 14 (MLP = 14).
// __launch_bounds__(256,3) grants ~84 regs so all 14 loads stay in flight.
// Cross-slice parity combination happens in the 12KB smem reduction.
// stats j: 0=EE 1=EO 2=OE 3=OO 4=R0E 5=R0O 6=C0E 7=C0O 8=P00
// ---------------------------------------------------------------------------
__global__ __launch_bounds__(256, 3) void k_stats(const float* __restrict__ in,
                                                  const float* __restrict__ conv_w,
                                                  const float* __restrict__ fc_w)
{
    const int tid = threadIdx.x;

    if (blockIdx.y == BATCH) {
        // ---- fused k_weff: fold conv_w [3,3,256,64] with fc_w [64,4] ----
        if (blockIdx.x >= 9) return;
        __shared__ float sf[CONV_OUT * ROUTES];
        const int k  = blockIdx.x;
        sf[tid] = fc_w[tid];
        __syncthreads();
        const float* cw = conv_w + ((size_t)k * CDIM + tid) * CONV_OUT;
        float a0 = 0.f, a1 = 0.f, a2 = 0.f, a3 = 0.f;
        #pragma unroll 16
        for (int co = 0; co < CONV_OUT; ++co) {
            float wv = cw[co];
            a0 += wv * sf[co * 4 + 0];
            a1 += wv * sf[co * 4 + 1];
            a2 += wv * sf[co * 4 + 2];
            a3 += wv * sf[co * 4 + 3];
        }
        const float inv = 1.0f / 784.0f;
        float* o = g_W + ((size_t)k * CDIM + tid) * ROUTES;
        o[0] = a0 * inv; o[1] = a1 * inv; o[2] = a2 * inv; o[3] = a3 * inv;
        return;
    }

    const int b  = blockIdx.y;
    const int g  = blockIdx.x;            // 0..13
    const int c4 = tid & 63;
    const int s  = tid >> 6;              // row within group, 0..3

    const int h = g * 4 + s;
    const float4* row = (const float4*)(in
        + (((size_t)b * HDIM + h) * WDIM) * CDIM) + c4;

    float4 Z = {0.f, 0.f, 0.f, 0.f};
    float4 sE = Z, sO = Z, c0 = Z;

    #pragma unroll
    for (int i = 0; i < 4; ++i) {
        // 14 independent loads issued before any accumulation (MLP = 14)
        float4 v[14];
        #pragma unroll
        for (int j = 0; j < 14; ++j)
            v[j] = row[(size_t)(14 * i + j) * (CDIM/4)];
        if (i == 0) c0 = v[0];
        // col index = 14*i + j: 14*i even, so parity follows j
        #pragma unroll
        for (int j = 0; j < 14; j += 2) {
            sE.x += v[j].x; sE.y += v[j].y; sE.z += v[j].z; sE.w += v[j].w;
            sO.x += v[j+1].x; sO.y += v[j+1].y; sO.z += v[j+1].z; sO.w += v[j+1].w;
        }
    }

    // Reduce the 4 row-slices, combining by row parity. 12 KB smem.
    __shared__ float4 sm[4][3][64];
    sm[s][0][c4] = sE;
    sm[s][1][c4] = sO;
    sm[s][2][c4] = c0;
    __syncthreads();

    if (tid < 64) {
        float4 e0 = sm[0][0][tid], o0 = sm[0][1][tid], z0 = sm[0][2][tid]; // row g*4+0 (even)
        float4 e1 = sm[1][0][tid], o1 = sm[1][1][tid], z1 = sm[1][2][tid]; // row g*4+1 (odd)
        float4 e2 = sm[2][0][tid], o2 = sm[2][1][tid], z2 = sm[2][2][tid]; // row g*4+2 (even)
        float4 e3 = sm[3][0][tid], o3 = sm[3][1][tid], z3 = sm[3][2][tid]; // row g*4+3 (odd)

        float4 st[NSTAT];
        st[0].x = e0.x + e2.x; st[0].y = e0.y + e2.y; st[0].z = e0.z + e2.z; st[0].w = e0.w + e2.w;
        st[1].x = o0.x + o2.x; st[1].y = o0.y + o2.y; st[1].z = o0.z + o2.z; st[1].w = o0.w + o2.w;
        st[2].x = e1.x + e3.x; st[2].y = e1.y + e3.y; st[2].z = e1.z + e3.z; st[2].w = e1.w + e3.w;
        st[3].x = o1.x + o3.x; st[3].y = o1.y + o3.y; st[3].z = o1.z + o3.z; st[3].w = o1.w + o3.w;
        st[6].x = z0.x + z2.x; st[6].y = z0.y + z2.y; st[6].z = z0.z + z2.z; st[6].w = z0.w + z2.w;
        st[7].x = z1.x + z3.x; st[7].y = z1.y + z3.y; st[7].z = z1.z + z3.z; st[7].w = z1.w + z3.w;
        float4 Z4 = {0.f, 0.f, 0.f, 0.f};
        st[4] = (g == 0) ? e0 : Z4;   // R0E
        st[5] = (g == 0) ? o0 : Z4;   // R0O
        st[8] = (g == 0) ? z0 : Z4;   // P00

        float4* p = (float4*)(g_part + (((size_t)b * ROWG + g) * NSTAT) * CDIM) + tid;
        #pragma unroll
        for (int j = 0; j < NSTAT; ++j)
            p[(size_t)j * (CDIM/4)] = st[j];
    }
}

// ---------------------------------------------------------------------------
// Kernel 2: per-batch routing logits + argmax.
// grid 64 blocks x 512 threads: thread = (half = tid>>8, ci = tid&255).
// Half h sums groups [h*7, h*7+7). Bias terms added only by half 0.
// ---------------------------------------------------------------------------
__global__ __launch_bounds__(512) void k_route(const float* __restrict__ gamma,
                                               const float* __restrict__ beta,
                                               const float* __restrict__ mmean,
                                               const float* __restrict__ mvar,
                                               const float* __restrict__ conv_b,
                                               const float* __restrict__ fc_w,
                                               const float* __restrict__ fc_b,
                                               float* __restrict__ out_routing)
{
    const int b    = blockIdx.x;
    const int tid  = threadIdx.x;
    const int ci   = tid & 255;
    const int half = tid >> 8;            // 0 or 1

    // Folded weights for this channel: W[k][r], k = kh*3+kw
    float W[9][ROUTES];
    #pragma unroll
    for (int k = 0; k < 9; ++k) {
        const float* w = g_W + ((size_t)k * CDIM + ci) * ROUTES;
        #pragma unroll
        for (int r = 0; r < ROUTES; ++r) W[k][r] = w[r];
    }

    const float scale = rsqrtf(mvar[ci] + BN_EPS) * gamma[ci];

    // Sum partial stats over this half's 7 groups (63 independent loads)
    float st[NSTAT];
    #pragma unroll
    for (int j = 0; j < NSTAT; ++j) st[j] = 0.f;
    const float* p = g_part + ((size_t)b * ROWG + half * 7) * NSTAT * CDIM + ci;
    #pragma unroll
    for (int g = 0; g < 7; ++g) {
        #pragma unroll
        for (int j = 0; j < NSTAT; ++j)
            st[j] += p[((size_t)g * NSTAT + j) * CDIM];
    }

    float acc[ROUTES];
    #pragma unroll
    for (int r = 0; r < ROUTES; ++r) {
        // Inclusion-exclusion coefficients (k = kh*3 + kw)
        float tEE  = W[0][r] + W[2][r] + W[6][r] + W[8][r];
        float tEO  = W[1][r] + W[7][r];
        float tOE  = W[3][r] + W[5][r];
        float tOO  = W[4][r];
        float tR0E = -(W[6][r] + W[8][r]);
        float tR0O = -W[7][r];
        float tC0E = -(W[2][r] + W[8][r]);
        float tC0O = -W[5][r];
        float tP   = W[8][r];

        float dotv = st[0]*tEE + st[1]*tEO + st[2]*tOE + st[3]*tOO
                   + st[4]*tR0E + st[5]*tR0O + st[6]*tC0E + st[7]*tC0O
                   + st[8]*tP;

        acc[r] = scale * dotv;
    }

    // Batch-independent bias terms: only half 0 contributes (once per channel).
    if (half == 0) {
        const float offs = beta[ci] - mmean[ci] * scale;
        #pragma unroll
        for (int r = 0; r < ROUTES; ++r) {
            // valid-count-weighted sum for the BN offset term
            float nsum = 784.f * (W[0][r] + W[1][r] + W[3][r] + W[4][r])
                       + 756.f * (W[2][r] + W[5][r] + W[6][r] + W[7][r])
                       + 729.f *  W[8][r];
            acc[r] += offs * nsum;
        }
        if (ci < CONV_OUT) {
            float cb = conv_b[ci];
            #pragma unroll
            for (int r = 0; r < ROUTES; ++r) acc[r] += cb * fc_w[ci * ROUTES + r];
        }
        if (ci == 0) {
            #pragma unroll
            for (int r = 0; r < ROUTES; ++r) acc[r] += fc_b[r];
        }
    }

    // Block reduction over 512 threads
    #pragma unroll
    for (int r = 0; r < ROUTES; ++r) {
        #pragma unroll
        for (int o = 16; o > 0; o >>= 1)
            acc[r] += __shfl_xor_sync(0xFFFFFFFFu, acc[r], o);
    }
    __shared__ float red[16][ROUTES];
    const int wid = tid >> 5, lane = tid & 31;
    if (lane == 0) {
        #pragma unroll
        for (int r = 0; r < ROUTES; ++r) red[wid][r] = acc[r];
    }
    __syncthreads();
    if (tid == 0) {
        float v[ROUTES];
        #pragma unroll
        for (int r = 0; r < ROUTES; ++r) {
            float s = 0.f;
            #pragma unroll
            for (int w = 0; w < 16; ++w) s += red[w][r];
            v[r] = s;
        }
        int best = 0;
        float bv = v[0];
        #pragma unroll
        for (int r = 1; r < ROUTES; ++r)
            if (v[r] > bv) { bv = v[r]; best = r; }
        g_route[b] = best;
        #pragma unroll
        for (int r = 0; r < ROUTES; ++r) out_routing[b * ROUTES + r] = v[r];
    }
}

// ---------------------------------------------------------------------------
// Kernel 3: gather selected 64-channel slab. 4 float4 per thread (stride 256
// within block, 512B/warp/instruction coalesced) for high MLP. Reverse
// scheduled so the input tail (L2-resident after k_stats) is gathered first.
// grid (13, 64), 256 threads. Per batch: 12544 float4.
// ---------------------------------------------------------------------------
#define G_F4_PER_B (HDIM * WDIM * ROUTE_W / 4)   // 12544
__global__ __launch_bounds__(256) void k_gather(const float* __restrict__ in,
                                                float* __restrict__ out)
{
    const int b = (BATCH - 1) - blockIdx.y;
    const int route = g_route[b];
    const int bx = (gridDim.x - 1) - blockIdx.x;
    const int base = bx * 1024 + threadIdx.x;

    const float4* src4 = (const float4*)in + (size_t)b * (HDIM * WDIM) * (CDIM / 4)
                       + route * (ROUTE_W / 4);
    float4* dst4 = (float4*)out + (size_t)b * G_F4_PER_B;

    #pragma unroll
    for (int m = 0; m < 4; ++m) {
        const int t = base + m * 256;
        if (t < G_F4_PER_B) {
            const int pixel = t >> 4;
            const int q = t & 15;
            dst4[t] = src4[(size_t)pixel * (CDIM / 4) + q];
        }
    }
}

// ---------------------------------------------------------------------------
extern "C" void kernel_launch(void* const* d_in, const int* in_sizes, int n_in,
                              void* d_out, int out_size)
{
    const float* inputs  = (const float*)d_in[0];
    const float* gamma   = (const float*)d_in[1];
    const float* beta    = (const float*)d_in[2];
    const float* mmean   = (const float*)d_in[3];
    const float* mvar    = (const float*)d_in[4];
    const float* conv_w  = (const float*)d_in[5];
    const float* conv_b  = (const float*)d_in[6];
    const float* fc_w    = (const float*)d_in[7];
    const float* fc_b    = (const float*)d_in[8];

    float* out = (float*)d_out;
    // output layout: x [64,56,56,64] then routing_x [64,4]
    float* out_routing = out + ((size_t)out_size - BATCH * ROUTES);

    k_stats<<<dim3(ROWG, BATCH + 1), 256>>>(inputs, conv_w, fc_w);
    k_route<<<BATCH, 512>>>(gamma, beta, mmean, mvar, conv_b, fc_w, fc_b, out_routing);
    k_gather<<<dim3((G_F4_PER_B + 1023) / 1024, BATCH), 256>>>(inputs, out);
}